// round 2
// baseline (speedup 1.0000x reference)
#include <cuda_runtime.h>
#include <cstdint>

#define FULL 0xffffffffu

// 54 accumulators (s[9] + upper-tri M[45]), each padded to 32 doubles (256B)
// so the atomic targets land in distinct L2 partitions.
__device__ double g_mom[54 * 32];
// Folded per-channel params: rows 0..3 = folded point weights (x,y,z,r),
// rows 4..8 = a*W[4..8] (for per-pillar constant), row 9 = BN bias b.
__device__ float g_params[10 * 64];

__global__ void k_zero() {
    int i = blockIdx.x * blockDim.x + threadIdx.x;
    if (i < 54 * 32) g_mom[i] = 0.0;
}

// ---------------------------------------------------------------------------
// Pass 1: accumulate s (9) and second-moment upper triangle (45) over all
// valid points. Masked points contribute zero (matching reference mask).
// points_mean sums ALL 32 points, divides by num_points (reference quirk).
// ---------------------------------------------------------------------------
__global__ __launch_bounds__(256) void k_moments(
    const float4* __restrict__ feat, const int* __restrict__ npts,
    const int* __restrict__ coors, int P)
{
    const int lane = threadIdx.x & 31;
    const int wid  = threadIdx.x >> 5;
    const int gw   = blockIdx.x * 8 + wid;
    const int nW   = gridDim.x * 8;

    float acc[54];
#pragma unroll
    for (int k = 0; k < 54; k++) acc[k] = 0.f;

    for (int p = gw; p < P; p += nW) {
        float4 f = feat[p * 32 + lane];
        int np = __ldg(npts + p);
        float sx = f.x, sy = f.y, sz = f.z;
#pragma unroll
        for (int o = 16; o > 0; o >>= 1) {
            sx += __shfl_xor_sync(FULL, sx, o);
            sy += __shfl_xor_sync(FULL, sy, o);
            sz += __shfl_xor_sync(FULL, sz, o);
        }
        float inv = 1.0f / (float)np;
        float mx = sx * inv, my = sy * inv, mz = sz * inv;
        int cy = __ldg(coors + p * 4 + 2);
        int cx = __ldg(coors + p * 4 + 3);
        float xc = (float)cx * 0.2f + 0.1f;
        float yc = (float)cy * 0.2f - 39.9f;

        if (lane < np) {
            float v[9];
            v[0] = f.x; v[1] = f.y; v[2] = f.z; v[3] = f.w;
            v[4] = f.x - mx; v[5] = f.y - my; v[6] = f.z - mz;
            v[7] = f.x - xc; v[8] = f.y - yc;
#pragma unroll
            for (int i = 0; i < 9; i++) acc[i] += v[i];
            int k = 9;
#pragma unroll
            for (int i = 0; i < 9; i++)
#pragma unroll
                for (int j = i; j < 9; j++) { acc[k] += v[i] * v[j]; k++; }
        }
    }

    // warp reduce all 54
#pragma unroll
    for (int k = 0; k < 54; k++) {
#pragma unroll
        for (int o = 16; o > 0; o >>= 1)
            acc[k] += __shfl_down_sync(FULL, acc[k], o);
    }

    __shared__ float red[8][54];
    if (lane == 0) {
#pragma unroll
        for (int k = 0; k < 54; k++) red[wid][k] = acc[k];
    }
    __syncthreads();
    for (int k = threadIdx.x; k < 54; k += blockDim.x) {
        float s = 0.f;
#pragma unroll
        for (int w = 0; w < 8; w++) s += red[w][k];
        atomicAdd(&g_mom[k * 32], (double)s);
    }
}

// ---------------------------------------------------------------------------
// Pass 2: compute BN stats exactly from moments, fold BN affine + feature
// structure into 10 per-channel params.
//   t_c(point) = x*A + y*B + z*C + r*D + K_c(pillar)
//   A = a*(w0+w4+w7), B = a*(w1+w5+w8), C = a*(w2+w6), D = a*w3
//   K_c = b - mx*a*w4 - my*a*w5 - mz*a*w6 - xc*a*w7 - yc*a*w8
// ---------------------------------------------------------------------------
__global__ void k_params(const float* __restrict__ W, const float* __restrict__ gam,
                         const float* __restrict__ bet, int P)
{
    int c = threadIdx.x;
    if (c >= 64) return;
    double s[9], M[9][9];
#pragma unroll
    for (int i = 0; i < 9; i++) s[i] = g_mom[i * 32];
    int idx = 9;
#pragma unroll
    for (int i = 0; i < 9; i++)
#pragma unroll
        for (int j = i; j < 9; j++) {
            double m = g_mom[idx * 32]; idx++;
            M[i][j] = m; M[j][i] = m;
        }
    double w[9];
#pragma unroll
    for (int i = 0; i < 9; i++) w[i] = (double)W[i * 64 + c];
    double cnt = (double)P * 32.0;
    double mean = 0.0;
#pragma unroll
    for (int i = 0; i < 9; i++) mean += s[i] * w[i];
    mean /= cnt;
    double ex2 = 0.0;
#pragma unroll
    for (int i = 0; i < 9; i++) {
        double t = 0.0;
#pragma unroll
        for (int j = 0; j < 9; j++) t += M[i][j] * w[j];
        ex2 += w[i] * t;
    }
    ex2 /= cnt;
    double var = ex2 - mean * mean;
    double a = (double)gam[c] / sqrt(var + 1e-3);
    double b = (double)bet[c] - mean * a;

    g_params[0 * 64 + c] = (float)(a * (w[0] + w[4] + w[7]));
    g_params[1 * 64 + c] = (float)(a * (w[1] + w[5] + w[8]));
    g_params[2 * 64 + c] = (float)(a * (w[2] + w[6]));
    g_params[3 * 64 + c] = (float)(a * w[3]);
    g_params[4 * 64 + c] = (float)(a * w[4]);
    g_params[5 * 64 + c] = (float)(a * w[5]);
    g_params[6 * 64 + c] = (float)(a * w[6]);
    g_params[7 * 64 + c] = (float)(a * w[7]);
    g_params[8 * 64 + c] = (float)(a * w[8]);
    g_params[9 * 64 + c] = (float)b;
}

// ---------------------------------------------------------------------------
// Pass 3: per-pillar output. One warp per pillar; lane handles channels
// (2*lane, 2*lane+1) as a packed f32x2 pair. Points staged in smem as
// duplicated pairs so the mainloop is pure LDS.128 + fma.rn.f32x2.
// Padded points contribute relu(b) to the max (x=0 row under BN).
// ---------------------------------------------------------------------------
__global__ __launch_bounds__(256) void k_out(
    const float4* __restrict__ feat, const int* __restrict__ npts,
    const int* __restrict__ coors, float* __restrict__ out, int P)
{
    __shared__ float4 sm[8][32][2];
    const int lane = threadIdx.x & 31;
    const int wid  = threadIdx.x >> 5;
    int p = blockIdx.x * 8 + wid;
    if (p >= P) return;

    float4 f = feat[p * 32 + lane];
    int np = __ldg(npts + p);
    float sx = f.x, sy = f.y, sz = f.z;
#pragma unroll
    for (int o = 16; o > 0; o >>= 1) {
        sx += __shfl_xor_sync(FULL, sx, o);
        sy += __shfl_xor_sync(FULL, sy, o);
        sz += __shfl_xor_sync(FULL, sz, o);
    }
    float inv = 1.0f / (float)np;
    float mx = sx * inv, my = sy * inv, mz = sz * inv;
    int cy = __ldg(coors + p * 4 + 2);
    int cx = __ldg(coors + p * 4 + 3);
    float xc = (float)cx * 0.2f + 0.1f;
    float yc = (float)cy * 0.2f - 39.9f;

    sm[wid][lane][0] = make_float4(f.x, f.x, f.y, f.y);
    sm[wid][lane][1] = make_float4(f.z, f.z, f.w, f.w);
    __syncwarp();

    const float2* pp = (const float2*)g_params;
    float2 q0 = pp[0 * 32 + lane];
    float2 q1 = pp[1 * 32 + lane];
    float2 q2 = pp[2 * 32 + lane];
    float2 q3 = pp[3 * 32 + lane];
    float2 q4 = pp[4 * 32 + lane];
    float2 q5 = pp[5 * 32 + lane];
    float2 q6 = pp[6 * 32 + lane];
    float2 q7 = pp[7 * 32 + lane];
    float2 q8 = pp[8 * 32 + lane];
    float2 bb = pp[9 * 32 + lane];

    float K0 = bb.x - mx * q4.x - my * q5.x - mz * q6.x - xc * q7.x - yc * q8.x;
    float K1 = bb.y - mx * q4.y - my * q5.y - mz * q6.y - xc * q7.y - yc * q8.y;

    unsigned long long w0, w1, w2, w3, kk;
    asm("mov.b64 %0, {%1,%2};" : "=l"(w0) : "f"(q0.x), "f"(q0.y));
    asm("mov.b64 %0, {%1,%2};" : "=l"(w1) : "f"(q1.x), "f"(q1.y));
    asm("mov.b64 %0, {%1,%2};" : "=l"(w2) : "f"(q2.x), "f"(q2.y));
    asm("mov.b64 %0, {%1,%2};" : "=l"(w3) : "f"(q3.x), "f"(q3.y));
    asm("mov.b64 %0, {%1,%2};" : "=l"(kk) : "f"(K0), "f"(K1));

    float m0, m1;
    if (np < 32) { m0 = bb.x; m1 = bb.y; }
    else { m0 = __int_as_float(0xff800000); m1 = __int_as_float(0xff800000); }

    const ulonglong2* sp = (const ulonglong2*)&sm[wid][0][0];
#pragma unroll 4
    for (int n = 0; n < np; n++) {
        ulonglong2 qa = sp[2 * n];       // (x,x),(y,y)
        ulonglong2 qb = sp[2 * n + 1];   // (z,z),(r,r)
        unsigned long long t;
        asm("fma.rn.f32x2 %0, %1, %2, %3;" : "=l"(t) : "l"(qa.x), "l"(w0), "l"(kk));
        asm("fma.rn.f32x2 %0, %1, %2, %0;" : "+l"(t) : "l"(qa.y), "l"(w1));
        asm("fma.rn.f32x2 %0, %1, %2, %0;" : "+l"(t) : "l"(qb.x), "l"(w2));
        asm("fma.rn.f32x2 %0, %1, %2, %0;" : "+l"(t) : "l"(qb.y), "l"(w3));
        float tl, th;
        asm("mov.b64 {%0,%1}, %2;" : "=f"(tl), "=f"(th) : "l"(t));
        m0 = fmaxf(m0, tl);
        m1 = fmaxf(m1, th);
    }

    ((float2*)out)[p * 32 + lane] = make_float2(fmaxf(m0, 0.f), fmaxf(m1, 0.f));
}

extern "C" void kernel_launch(void* const* d_in, const int* in_sizes, int n_in,
                              void* d_out, int out_size) {
    const float4* feat  = (const float4*)d_in[0];
    const int*    npts  = (const int*)d_in[1];
    const int*    coors = (const int*)d_in[2];
    const float*  W     = (const float*)d_in[3];
    const float*  gam   = (const float*)d_in[4];
    const float*  bet   = (const float*)d_in[5];
    float* out = (float*)d_out;
    int P = in_sizes[1];

    k_zero<<<7, 256>>>();
    k_moments<<<296, 256>>>(feat, npts, coors, P);
    k_params<<<1, 64>>>(W, gam, bet, P);
    k_out<<<(P + 7) / 8, 256>>>(feat, npts, coors, out, P);
}